// round 1
// baseline (speedup 1.0000x reference)
#include <cuda_runtime.h>
#include <math.h>

#define NB 4
#define NE 100000
#define NT 100000
#define ND 64
#define NSTEPS 2
#define HSZ 4096         // power of 2; expected live entries ~4-10
#define MAX1 4096
#define MAX2 16384
#define EPSV 1e-6f

// scratch state (device globals; re-initialized every launch by k_init)
__device__ int   g_s0[NB];
__device__ float g_cq[NSTEPS][NB][ND];
__device__ int   g_cnt1;
__device__ int   g_cnt2;
__device__ int   g_list1[MAX1];
__device__ int   g_list2[MAX2];
__device__ int   g_hkey[HSZ];
__device__ float g_hep[HSZ];
__device__ float g_hhist[HSZ][ND];

__device__ __forceinline__ float sigm(float x) { return 1.0f / (1.0f + expf(-x)); }

__device__ __forceinline__ int hinsert(int key) {
    unsigned h = ((unsigned)key * 2654435761u) & (HSZ - 1);
    for (int p = 0; p < HSZ; p++) {
        int prev = atomicCAS(&g_hkey[h], -1, key);
        if (prev == -1 || prev == key) return (int)h;
        h = (h + 1) & (HSZ - 1);
    }
    return -1;
}

__device__ __forceinline__ int hfind(int key) {
    unsigned h = ((unsigned)key * 2654435761u) & (HSZ - 1);
    for (int p = 0; p < HSZ; p++) {
        int k = g_hkey[h];
        if (k == key) return (int)h;
        if (k == -1) return -1;
        h = (h + 1) & (HSZ - 1);
    }
    return -1;
}

// K1: zero output, find one-hot start entity per batch, clear hash/counters,
//     and (block 0) compute cq[step][b][:] = tanh(rel_emb[query[b]] @ W_step[step] + b_step[step])
__global__ void k_init(const float* __restrict__ start, const float* __restrict__ rel_emb,
                       const float* __restrict__ W_step, const float* __restrict__ b_step,
                       const int* __restrict__ query, float* __restrict__ out)
{
    int idx = blockIdx.x * blockDim.x + threadIdx.x;
    if (idx < NB * NE) {
        out[idx] = 0.0f;
        if (start[idx] != 0.0f) g_s0[idx / NE] = idx % NE;
    }
    if (idx < HSZ) { g_hkey[idx] = -1; g_hep[idx] = 0.0f; }
    if (idx < HSZ * ND) ((float*)g_hhist)[idx] = 0.0f;   // HSZ*ND = 262144 < NB*NE
    if (idx == 0) { g_cnt1 = 0; g_cnt2 = 0; }

    if (blockIdx.x == 0) {
        for (int o = threadIdx.x; o < NSTEPS * NB * ND; o += blockDim.x) {
            int step = o / (NB * ND);
            int rem  = o % (NB * ND);
            int b = rem / ND, j = rem % ND;
            int q = query[b];
            float acc = b_step[step * ND + j];
            #pragma unroll 8
            for (int i = 0; i < ND; i++)
                acc += rel_emb[q * ND + i] * W_step[(step * ND + i) * ND + j];
            g_cq[step][b][j] = tanhf(acc);
        }
    }
}

// K2: collect triples whose subject equals a batch's start entity
__global__ void k_hop1_collect(const int* __restrict__ kb)
{
    int t = blockIdx.x * blockDim.x + threadIdx.x;
    if (t >= NT) return;
    int s = kb[3 * t];
    #pragma unroll
    for (int b = 0; b < NB; b++) {
        if (s == g_s0[b]) {
            int i = atomicAdd(&g_cnt1, 1);
            if (i < MAX1) g_list1[i] = t * 4 + b;
        }
    }
}

// K3: step-0 GRU cell (h = 0) on each hop-1 triple; accumulate sparse (ep, hist) into hash.
// One 64-thread block per entry, thread = feature index d.
__global__ void k_hop1_proc(const int* __restrict__ kb, const float* __restrict__ rel_emb,
                            const float* __restrict__ w_ih, const float* __restrict__ b_ih,
                            const float* __restrict__ b_hh, const float* __restrict__ w_cls,
                            const float* __restrict__ b_cls)
{
    __shared__ float s_rf[ND];
    __shared__ float s_red[ND];
    __shared__ int   s_slot;
    __shared__ float s_objp;
    int n = min(g_cnt1, MAX1);
    int d = threadIdx.x;
    for (int i = blockIdx.x; i < n; i += gridDim.x) {
        int code = g_list1[i];
        int t = code >> 2, b = code & 3;
        int e = kb[3 * t + 1], rid = kb[3 * t + 2];

        s_rf[d] = rel_emb[rid * ND + d];
        __syncthreads();

        float xr = b_ih[d], xz = b_ih[ND + d], xn = b_ih[2 * ND + d];
        const float* wr = w_ih + d * ND;
        const float* wz = w_ih + (ND + d) * ND;
        const float* wn = w_ih + (2 * ND + d) * ND;
        #pragma unroll 8
        for (int k = 0; k < ND; k++) {
            float f = s_rf[k];
            xr += f * wr[k]; xz += f * wz[k]; xn += f * wn[k];
        }
        // h = 0 -> h_proj = b_hh
        float r  = sigm(xr + b_hh[d]);
        float z  = sigm(xz + b_hh[ND + d]);
        float nn = tanhf(xn + r * b_hh[2 * ND + d]);
        float trans = (1.0f - z) * nn;            // + z*h with h=0

        s_red[d] = trans * g_cq[0][b][d] * w_cls[d];
        __syncthreads();
        if (d == 0) {
            float logit = b_cls[0];
            for (int k = 0; k < ND; k++) logit += s_red[k];
            float p = sigm(logit);                // obj_p = start(=1) * p
            s_objp = p;
            s_slot = hinsert(b * NE + e);
            if (s_slot >= 0) atomicAdd(&g_hep[s_slot], p);
        }
        __syncthreads();
        if (s_slot >= 0) atomicAdd(&g_hhist[s_slot][d], trans * s_objp);
        __syncthreads();
    }
}

// K4: collect triples whose subject is in the hop-1 support
__global__ void k_hop2_collect(const int* __restrict__ kb)
{
    int t = blockIdx.x * blockDim.x + threadIdx.x;
    if (t >= NT) return;
    int s = kb[3 * t];
    #pragma unroll
    for (int b = 0; b < NB; b++) {
        if (hfind(b * NE + s) >= 0) {
            int i = atomicAdd(&g_cnt2, 1);
            if (i < MAX2) g_list2[i] = t * 4 + b;
        }
    }
}

// K5: step-1 full GRU cell on each hop-2 triple; accumulate obj_ep into output.
__global__ void k_hop2_proc(const int* __restrict__ kb, const float* __restrict__ rel_emb,
                            const float* __restrict__ w_ih, const float* __restrict__ w_hh,
                            const float* __restrict__ b_ih, const float* __restrict__ b_hh,
                            const float* __restrict__ w_cls, const float* __restrict__ b_cls,
                            float* __restrict__ out)
{
    __shared__ float s_rf[ND], s_h[ND], s_red[ND];
    __shared__ int s_slot;
    int n = min(g_cnt2, MAX2);
    int d = threadIdx.x;
    for (int i = blockIdx.x; i < n; i += gridDim.x) {
        int code = g_list2[i];
        int t = code >> 2, b = code & 3;
        int s = kb[3 * t], e = kb[3 * t + 1], rid = kb[3 * t + 2];

        if (d == 0) s_slot = hfind(b * NE + s);   // guaranteed found
        __syncthreads();
        int slot = s_slot;
        float ep = g_hep[slot];
        s_h[d]  = g_hhist[slot][d] / (ep + EPSV); // hist = seg(obj_feat)/(obj_ep+eps)
        s_rf[d] = rel_emb[rid * ND + d];
        __syncthreads();

        float xr = b_ih[d], xz = b_ih[ND + d], xn = b_ih[2 * ND + d];
        float hr = b_hh[d], hz = b_hh[ND + d], hn = b_hh[2 * ND + d];
        const float* wir = w_ih + d * ND;
        const float* wiz = w_ih + (ND + d) * ND;
        const float* win = w_ih + (2 * ND + d) * ND;
        const float* whr = w_hh + d * ND;
        const float* whz = w_hh + (ND + d) * ND;
        const float* whn = w_hh + (2 * ND + d) * ND;
        #pragma unroll 4
        for (int k = 0; k < ND; k++) {
            float f = s_rf[k], hh = s_h[k];
            xr += f * wir[k]; xz += f * wiz[k]; xn += f * win[k];
            hr += hh * whr[k]; hz += hh * whz[k]; hn += hh * whn[k];
        }
        float r  = sigm(xr + hr);
        float z  = sigm(xz + hz);
        float nn = tanhf(xn + r * hn);
        float hd = s_h[d];
        float trans = (1.0f - z) * nn + z * hd;

        s_red[d] = trans * g_cq[1][b][d] * w_cls[d];
        __syncthreads();
        if (d == 0) {
            float logit = b_cls[0];
            for (int k = 0; k < ND; k++) logit += s_red[k];
            float p = sigm(logit);
            float last0 = fminf(ep, 1.0f);        // = obj_ep/zden
            atomicAdd(&out[b * NE + e], last0 * p);
        }
        __syncthreads();
    }
}

// K6: last_e = obj_ep / (m*obj_ep + (1-m))  ==  min(obj_ep, 1)
__global__ void k_final(float* __restrict__ out)
{
    int idx = blockIdx.x * blockDim.x + threadIdx.x;
    if (idx < NB * NE) out[idx] = fminf(out[idx], 1.0f);
}

extern "C" void kernel_launch(void* const* d_in, const int* in_sizes, int n_in,
                              void* d_out, int out_size)
{
    const float* start   = (const float*)d_in[0];
    const float* rel_emb = (const float*)d_in[1];
    const float* W_step  = (const float*)d_in[2];
    const float* b_step  = (const float*)d_in[3];
    const float* w_ih    = (const float*)d_in[4];
    const float* w_hh    = (const float*)d_in[5];
    const float* b_ih    = (const float*)d_in[6];
    const float* b_hh    = (const float*)d_in[7];
    const float* w_cls   = (const float*)d_in[8];
    const float* b_cls   = (const float*)d_in[9];
    const int*   query   = (const int*)d_in[10];
    const int*   kb      = (const int*)d_in[11];
    float* out = (float*)d_out;

    k_init<<<(NB * NE + 255) / 256, 256>>>(start, rel_emb, W_step, b_step, query, out);
    k_hop1_collect<<<(NT + 255) / 256, 256>>>(kb);
    k_hop1_proc<<<128, ND>>>(kb, rel_emb, w_ih, b_ih, b_hh, w_cls, b_cls);
    k_hop2_collect<<<(NT + 255) / 256, 256>>>(kb);
    k_hop2_proc<<<256, ND>>>(kb, rel_emb, w_ih, w_hh, b_ih, b_hh, w_cls, b_cls, out);
    k_final<<<(NB * NE + 255) / 256, 256>>>(out);
}